// round 2
// baseline (speedup 1.0000x reference)
#include <cuda_runtime.h>
#include <cstdint>

#define BB 16
#define FM 32
#define CC 128
#define HW 3136
#define ETA 0.1f
#define ALPHA_ 0.1f
#define THETA_ 0.1f
#define EPSF 1e-10f

// ------------- scratch (static device globals; no allocation) -------------
__device__ float g_Ab[BB*CC*HW];        // clip(tile(symm_pad(A,2)) + eta*noise, 0)
__device__ float g_s[BB*CC];            // per-(b,c) spatial sum
__device__ int   g_fm[BB*FM];           // winner channel per (b,f)
__device__ float g_A2p[BB*FM*60*60];    // pad_activations of masked winner maps
__device__ float g_Kch[CC*CC*25];       // K_change [c][a][x*5+y]
__device__ float g_W2[CC*CC*25];        // conv2 weights [o][i][t]

// symm_pad(.,2) index map on a 56 axis: 0->3, 1->2, 54->53, 55->52
__device__ __forceinline__ int m56(int h) {
    return h < 2 ? 3 - h : (h >= 54 ? 107 - h : h);
}
// pad_activations row/col map on the 60 axis (includes the clobbering semantics)
__device__ __forceinline__ int m60(int r) {
    return r < 4 ? 5 - r : (r < 56 ? r - 2 : 109 - r);
}

// ---------------- kernel 1: Ab + per-channel sums ----------------
__global__ void k_prep(const float* __restrict__ A, const float* __restrict__ noise) {
    int bid = blockIdx.x;              // b*128 + c
    int b = bid >> 7, c = bid & 127;
    int f = c & 31;
    const float* Ap = A + (size_t)(b*FM + f)*HW;
    const float* Np = noise + (size_t)bid*HW;
    float* Op = g_Ab + (size_t)bid*HW;
    float sum = 0.f;
    for (int idx = threadIdx.x; idx < HW; idx += 256) {
        int h = idx / 56, w = idx - h*56;
        float v = fmaxf(Ap[m56(h)*56 + m56(w)] + ETA*Np[idx], 0.f);
        Op[idx] = v;
        sum += v;
    }
    __shared__ float red[8];
    #pragma unroll
    for (int o = 16; o; o >>= 1) sum += __shfl_xor_sync(~0u, sum, o);
    if ((threadIdx.x & 31) == 0) red[threadIdx.x >> 5] = sum;
    __syncthreads();
    if (threadIdx.x < 8) {
        float s2 = red[threadIdx.x];
        #pragma unroll
        for (int o = 4; o; o >>= 1) s2 += __shfl_xor_sync(0xffu, s2, o);
        if (threadIdx.x == 0) g_s[bid] = s2;
    }
}

// ---------------- kernel: zero K_change accumulator ----------------
__global__ void k_zero() {
    int i = blockIdx.x*blockDim.x + threadIdx.x;
    if (i < CC*CC*25) g_Kch[i] = 0.f;
}

// ---------------- kernel 2: winners (softmax sums to 1 -> argmax on sum(Ab)) ----
__global__ void k_win() {
    int t = threadIdx.x;               // b*32 + f
    int b = t >> 5, f = t & 31;
    float best = g_s[b*CC + f];
    int wr = 0;
    #pragma unroll
    for (int r = 1; r < 4; r++) {
        float v = g_s[b*CC + r*FM + f];
        if (v > best) { best = v; wr = r; }
    }
    g_fm[t] = wr*FM + f;
}

// ---------------- kernel 3: padded winner maps (pad_activations(A2)) -------
__global__ void k_pad() {
    int bid = blockIdx.x;              // b*32 + slot
    int b = bid >> 5;
    int cb = g_fm[bid];
    const float* src = g_Ab + (size_t)(b*CC + cb)*HW;
    float* dst = g_A2p + (size_t)bid*3600;
    for (int idx = threadIdx.x; idx < 3600; idx += 256) {
        int r = idx / 60, cc2 = idx - r*60;
        dst[idx] = src[m60(r)*56 + m60(cc2)];
    }
}

// ---------------- kernel 4: K_change (dominant compute) ----------------
// grid (b=16, cwt=4, at=4); 256 threads = 8 winner-c x 32 a
__global__ void __launch_bounds__(256) k_kch() {
    int b = blockIdx.x, cwt = blockIdx.y, at = blockIdx.z;
    int tid = threadIdx.x;
    int al = tid & 31, cl = tid >> 5;
    int a0 = at*32;

    __shared__ float sAb[5][32][61];   // ring of Ab rows, zero halos, stride 61 (conflict-free)
    __shared__ float sAm[8][56];       // current Am row for the 8 winner channels
    __shared__ int   sC[8];

    if (tid < 8) sC[tid] = g_fm[b*FM + cwt*8 + tid];
    for (int i = tid; i < 5*32*61; i += 256) (&sAb[0][0][0])[i] = 0.f;
    __syncthreads();

    const float* AbB = g_Ab + (size_t)b*CC*HW;
    // prologue: rows 0,1 -> slots 0,1
    #pragma unroll
    for (int r = 0; r < 2; r++)
        for (int idx = tid; idx < 32*56; idx += 256) {
            int ch = idx / 56, col = idx - ch*56;
            sAb[r][ch][col+2] = AbB[(size_t)(a0+ch)*HW + r*56 + col];
        }

    float acc[5][5] = {};

    for (int h = 0; h < 56; h++) {
        // load Ab row h+2 (zeros beyond 55) into slot (h+2)%5
        {
            int row = h + 2, slot = row % 5;
            for (int idx = tid; idx < 32*56; idx += 256) {
                int ch = idx / 56, col = idx - ch*56;
                sAb[slot][ch][col+2] = (row < 56) ? AbB[(size_t)(a0+ch)*HW + row*56 + col] : 0.f;
            }
        }
        // load Am row h for the 8 winner channels
        for (int idx = tid; idx < 8*56; idx += 256) {
            int cj = idx / 56, col = idx - cj*56;
            sAm[cj][col] = AbB[(size_t)sC[cj]*HW + h*56 + col];
        }
        __syncthreads();

        const float* rx[5];
        #pragma unroll
        for (int x = 0; x < 5; x++) rx[x] = &sAb[(h + 7 - x) % 5][al][0];
        const float* am = sAm[cl];

        // register ring over columns: rg[x][j] holds smem cols w..w+4
        float rg[5][5];
        #pragma unroll
        for (int x = 0; x < 5; x++)
            #pragma unroll
            for (int j = 0; j < 5; j++) rg[x][j] = rx[x][j];

        #pragma unroll 1
        for (int wb = 0; wb < 55; wb += 5) {
            #pragma unroll
            for (int k = 0; k < 5; k++) {
                float a = am[wb + k];
                #pragma unroll
                for (int x = 0; x < 5; x++) {
                    #pragma unroll
                    for (int y = 0; y < 5; y++)
                        acc[x][y] = fmaf(a, rg[x][(k + 4 - y) % 5], acc[x][y]);
                    rg[x][k] = rx[x][wb + k + 5];
                }
            }
        }
        {   // w = 55 (ring phase k=0)
            float a = am[55];
            #pragma unroll
            for (int x = 0; x < 5; x++)
                #pragma unroll
                for (int y = 0; y < 5; y++)
                    acc[x][y] = fmaf(a, rg[x][(4 - y) % 5], acc[x][y]);
        }
        __syncthreads();
    }

    int c = g_fm[b*FM + cwt*8 + cl];
    float* dst = g_Kch + ((size_t)c*CC + (a0 + al))*25;
    #pragma unroll
    for (int x = 0; x < 5; x++)
        #pragma unroll
        for (int y = 0; y < 5; y++)
            atomicAdd(&dst[x*5 + y], acc[x][y] * (1.f/2048.f));
}

// ---------------- kernel 5: W2 = minmax(0.9*K1 + 0.1*minmax(K_change)) -----
__global__ void k_w2(const float* __restrict__ K) {
    int g = blockIdx.x*blockDim.x + threadIdx.x;
    if (g >= CC*CC) return;
    int o = g >> 7, i = g & 127;
    const float* kch = g_Kch + ((size_t)i*CC + o)*25;
    float v[25];
    float mn = 1e30f, mx = -1e30f;
    #pragma unroll
    for (int t = 0; t < 25; t++) { v[t] = kch[t]; mn = fminf(mn, v[t]); mx = fmaxf(mx, v[t]); }
    float inv = 1.f / (mx - mn + EPSF);
    const float* kk = K + ((size_t)o*CC + i)*25;   // K1[i][o] = K[o][i]
    float mn2 = 1e30f, mx2 = -1e30f;
    #pragma unroll
    for (int t = 0; t < 25; t++) {
        v[t] = (1.f - ALPHA_)*kk[t] + ALPHA_*((v[t] - mn)*inv);
        mn2 = fminf(mn2, v[t]); mx2 = fmaxf(mx2, v[t]);
    }
    float inv2 = 1.f / (mx2 - mn2 + EPSF);
    float* w = g_W2 + (size_t)g*25;
    #pragma unroll
    for (int t = 0; t < 25; t++) w[t] = (v[t] - mn2)*inv2;
}

// ---------------- kernel 6: winner-sparse conv2 + gather + output ---------
// grid (b=16, fg=2, pg=8); 128 threads = 16 f x 8 q-groups (7 outputs each)
__global__ void __launch_bounds__(128) k_out(float* __restrict__ out) {
    int b = blockIdx.x, fg = blockIdx.y, pg = blockIdx.z;
    int tid = threadIdx.x;
    int fl = tid >> 3, qg = tid & 7;
    int q0 = qg * 7;

    extern __shared__ float sh[];
    float* sIn = sh;                   // [5][32][61]
    float* sW  = sh + 5*32*61;         // [16][801]
    __shared__ int sFm[32];
    if (tid < 32) sFm[tid] = g_fm[b*FM + tid];
    __syncthreads();

    int f = fg*16 + fl;
    int cb = sFm[f];

    for (int idx = tid; idx < 16*32*25; idx += 128) {
        int fl2 = idx / 800;
        int rem = idx - fl2*800;
        int i = rem / 25, t = rem - i*25;
        sW[fl2*801 + i*25 + t] = g_W2[((size_t)sFm[fg*16 + fl2]*CC + sFm[i])*25 + t];
    }

    const float* pA = g_A2p + (size_t)b*FM*3600;
    int p0 = pg * 7;
    #pragma unroll
    for (int r = 0; r < 4; r++) {
        int row = p0 + r, slot = row % 5;
        for (int idx = tid; idx < 32*60; idx += 128) {
            int i = idx / 60, col = idx - i*60;
            sIn[(slot*32 + i)*61 + col] = pA[(size_t)i*3600 + row*60 + col];
        }
    }

    const float* wbase = sW + fl*801;
    for (int p = p0; p < p0 + 7; p++) {
        __syncthreads();
        {
            int row = p + 4, slot = row % 5;
            for (int idx = tid; idx < 32*60; idx += 128) {
                int i = idx / 60, col = idx - i*60;
                sIn[(slot*32 + i)*61 + col] = pA[(size_t)i*3600 + row*60 + col];
            }
        }
        __syncthreads();

        float acc[7] = {};
        #pragma unroll 1
        for (int i = 0; i < 32; i++) {
            #pragma unroll
            for (int u = 0; u < 5; u++) {
                const float* wr = wbase + i*25 + u*5;
                float w0 = wr[0], w1 = wr[1], w2 = wr[2], w3 = wr[3], w4 = wr[4];
                const float* rp = sIn + (((p + u) % 5)*32 + i)*61 + q0;
                #pragma unroll
                for (int cc = 0; cc < 11; cc++) {
                    float v = rp[cc];
                    if (cc <= 6)            acc[cc]   = fmaf(v, w0, acc[cc]);
                    if (cc >= 1 && cc <= 7) acc[cc-1] = fmaf(v, w1, acc[cc-1]);
                    if (cc >= 2 && cc <= 8) acc[cc-2] = fmaf(v, w2, acc[cc-2]);
                    if (cc >= 3 && cc <= 9) acc[cc-3] = fmaf(v, w3, acc[cc-3]);
                    if (cc >= 4)            acc[cc-4] = fmaf(v, w4, acc[cc-4]);
                }
            }
        }

        const float* a2row = g_Ab + (size_t)(b*CC + cb)*HW + p*56 + q0;
        float* orow = out + (size_t)((b*FM + f)*56 + p)*56 + q0;
        #pragma unroll
        for (int j = 0; j < 7; j++)
            orow[j] = a2row[j] + THETA_ * (acc[j] * (1.f/32.f));
    }
}

// ---------------- launch ----------------
extern "C" void kernel_launch(void* const* d_in, const int* in_sizes, int n_in,
                              void* d_out, int out_size) {
    const float* A     = (const float*)d_in[0];
    const float* K     = (const float*)d_in[1];
    const float* noise = (const float*)d_in[2];
    float* out = (float*)d_out;

    k_prep<<<BB*CC, 256>>>(A, noise);
    k_zero<<<(CC*CC*25 + 255)/256, 256>>>();
    k_win<<<1, BB*FM>>>();
    k_pad<<<BB*FM, 256>>>();
    k_kch<<<dim3(BB, 4, 4), 256>>>();
    k_w2<<<(CC*CC + 255)/256, 256>>>(K);

    const int smem = (5*32*61 + 16*801) * 4;   // 90304 bytes
    cudaFuncSetAttribute(k_out, cudaFuncAttributeMaxDynamicSharedMemorySize, smem);
    k_out<<<dim3(BB, 2, 8), 128, smem>>>(out);
}

// round 3
// speedup vs baseline: 1.0602x; 1.0602x over previous
#include <cuda_runtime.h>
#include <cstdint>

#define BB 16
#define FM 32
#define CC 128
#define HW 3136
#define ETA 0.1f
#define ALPHA_ 0.1f
#define THETA_ 0.1f
#define EPSF 1e-10f

typedef unsigned long long ull;

// ------------- scratch (static device globals; no allocation) -------------
__device__ float g_Ab[BB*CC*HW];        // clip(tile(symm_pad(A,2)) + eta*noise, 0)
__device__ float g_s[BB*CC];            // per-(b,c) spatial sum
__device__ int   g_fm[BB*FM];           // winner channel per (b,f)
__device__ float g_Kch[CC*CC*25];       // K_change [c][a][x*5+y]
__device__ float g_W2[CC*CC*25];        // conv2 weights [o][i][t]

// ---------------- packed f32x2 helpers ----------------
__device__ __forceinline__ ull pack2(float x, float y) {
    ull r; asm("mov.b64 %0, {%1,%2};" : "=l"(r) : "f"(x), "f"(y)); return r;
}
__device__ __forceinline__ void ffma2(ull& d, ull a, ull b) {
    asm("fma.rn.f32x2 %0, %1, %2, %3;" : "=l"(d) : "l"(a), "l"(b), "l"(d));
}
__device__ __forceinline__ float2 unpk(ull v) {
    float2 r; asm("mov.b64 {%0,%1}, %2;" : "=f"(r.x), "=f"(r.y) : "l"(v)); return r;
}

// symm_pad(.,2) index map on a 56 axis: 0->3, 1->2, 54->53, 55->52
__device__ __forceinline__ int m56(int h) {
    return h < 2 ? 3 - h : (h >= 54 ? 107 - h : h);
}
// pad_activations row/col map on the 60 axis (includes clobbering semantics)
__device__ __forceinline__ int m60(int r) {
    return r < 4 ? 5 - r : (r < 56 ? r - 2 : 109 - r);
}

// ---------------- kernel 1: Ab + per-channel sums ----------------
__global__ void k_prep(const float* __restrict__ A, const float* __restrict__ noise) {
    int bid = blockIdx.x;              // b*128 + c
    int b = bid >> 7, c = bid & 127;
    int f = c & 31;
    const float* Ap = A + (size_t)(b*FM + f)*HW;
    const float* Np = noise + (size_t)bid*HW;
    float* Op = g_Ab + (size_t)bid*HW;
    float sum = 0.f;
    for (int idx = threadIdx.x; idx < HW; idx += 256) {
        int h = idx / 56, w = idx - h*56;
        float v = fmaxf(Ap[m56(h)*56 + m56(w)] + ETA*Np[idx], 0.f);
        Op[idx] = v;
        sum += v;
    }
    __shared__ float red[8];
    #pragma unroll
    for (int o = 16; o; o >>= 1) sum += __shfl_xor_sync(~0u, sum, o);
    if ((threadIdx.x & 31) == 0) red[threadIdx.x >> 5] = sum;
    __syncthreads();
    if (threadIdx.x < 8) {
        float s2 = red[threadIdx.x];
        #pragma unroll
        for (int o = 4; o; o >>= 1) s2 += __shfl_xor_sync(0xffu, s2, o);
        if (threadIdx.x == 0) g_s[bid] = s2;
    }
}

// ---------------- zero K_change accumulator ----------------
__global__ void k_zero() {
    int i = blockIdx.x*blockDim.x + threadIdx.x;
    if (i < CC*CC*25) g_Kch[i] = 0.f;
}

// ---------------- winners (softmax sums to 1 -> argmax on sum(Ab)) --------
__global__ void k_win() {
    int t = threadIdx.x;               // b*32 + f
    int b = t >> 5, f = t & 31;
    float best = g_s[b*CC + f];
    int wr = 0;
    #pragma unroll
    for (int r = 1; r < 4; r++) {
        float v = g_s[b*CC + r*FM + f];
        if (v > best) { best = v; wr = r; }
    }
    g_fm[t] = wr*FM + f;
}

// ---------------- K_change: f32x2-packed cross-correlation ----------------
// grid (b=16, cwt=4, at=4); 128 threads = 8 winner-c x 16 a-pairs
__global__ void __launch_bounds__(128) k_kch() {
    int b = blockIdx.x, cwt = blockIdx.y, at = blockIdx.z;
    int tid = threadIdx.x;
    int al = tid & 15;                 // channel pair (2al, 2al+1)
    int cl = tid >> 4;                 // winner slot 0..7
    int a0 = at*32;

    __shared__ float sAb[5][61][34];   // [slot][paddedCol][channel], stride 34 = 8B-aligned pairs
    __shared__ ull   sAm2[8][56];      // winner rows duplicated {v,v}
    __shared__ int   sC[8];

    if (tid < 8) sC[tid] = g_fm[b*FM + cwt*8 + tid];
    for (int i = tid; i < 5*61*34; i += 128) (&sAb[0][0][0])[i] = 0.f;
    __syncthreads();

    const float* AbB = g_Ab + (size_t)b*CC*HW;
    // prologue: data rows 0,1 -> slots 0,1
    #pragma unroll
    for (int r = 0; r < 2; r++)
        for (int idx = tid; idx < 32*56; idx += 128) {
            int ch = idx / 56, col = idx - ch*56;
            sAb[r][col+2][ch] = AbB[(size_t)(a0+ch)*HW + r*56 + col];
        }

    ull acc[5][5];
    #pragma unroll
    for (int x = 0; x < 5; x++)
        #pragma unroll
        for (int y = 0; y < 5; y++) acc[x][y] = 0ull;

    for (int h = 0; h < 56; h++) {
        {   // load Ab row h+2 (zeros beyond 55) into slot (h+2)%5
            int row = h + 2, slot = row % 5;
            for (int idx = tid; idx < 32*56; idx += 128) {
                int ch = idx / 56, col = idx - ch*56;
                sAb[slot][col+2][ch] = (row < 56) ? AbB[(size_t)(a0+ch)*HW + row*56 + col] : 0.f;
            }
        }
        // winner (Am) row h, duplicated
        for (int idx = tid; idx < 8*56; idx += 128) {
            int cj = idx / 56, col = idx - cj*56;
            float v = AbB[(size_t)sC[cj]*HW + h*56 + col];
            sAm2[cj][col] = pack2(v, v);
        }
        __syncthreads();

        const char* rx[5];
        #pragma unroll
        for (int x = 0; x < 5; x++)
            rx[x] = (const char*)&sAb[(h + 7 - x) % 5][0][2*al];
        const ull* am = sAm2[cl];

        // register ring over columns (pairs): rg[x][j] holds smem cols w..w+4
        ull rg[5][5];
        #pragma unroll
        for (int x = 0; x < 5; x++)
            #pragma unroll
            for (int j = 0; j < 5; j++)
                rg[x][j] = *(const ull*)(rx[x] + j*136);   // 34 floats * 4B

        #pragma unroll 1
        for (int wb = 0; wb < 55; wb += 5) {
            #pragma unroll
            for (int k = 0; k < 5; k++) {
                ull a = am[wb + k];
                #pragma unroll
                for (int x = 0; x < 5; x++) {
                    #pragma unroll
                    for (int y = 0; y < 5; y++)
                        ffma2(acc[x][y], a, rg[x][(k + 4 - y) % 5]);
                    rg[x][k] = *(const ull*)(rx[x] + (wb + k + 5)*136);
                }
            }
        }
        {   // w = 55 (ring phase k=0)
            ull a = am[55];
            #pragma unroll
            for (int x = 0; x < 5; x++)
                #pragma unroll
                for (int y = 0; y < 5; y++)
                    ffma2(acc[x][y], a, rg[x][(4 - y) % 5]);
        }
        __syncthreads();
    }

    int c = sC[cl];
    float* dst = g_Kch + ((size_t)c*CC + (a0 + 2*al))*25;
    #pragma unroll
    for (int x = 0; x < 5; x++)
        #pragma unroll
        for (int y = 0; y < 5; y++) {
            float2 v = unpk(acc[x][y]);
            atomicAdd(&dst[x*5 + y],      v.x * (1.f/2048.f));
            atomicAdd(&dst[25 + x*5 + y], v.y * (1.f/2048.f));
        }
}

// ---------------- W2 = minmax(0.9*K1 + 0.1*minmax(K_change)) ---------------
__global__ void k_w2(const float* __restrict__ K) {
    int g = blockIdx.x*blockDim.x + threadIdx.x;
    if (g >= CC*CC) return;
    int o = g >> 7, i = g & 127;
    const float* kch = g_Kch + ((size_t)i*CC + o)*25;
    float v[25];
    float mn = 1e30f, mx = -1e30f;
    #pragma unroll
    for (int t = 0; t < 25; t++) { v[t] = kch[t]; mn = fminf(mn, v[t]); mx = fmaxf(mx, v[t]); }
    float inv = 1.f / (mx - mn + EPSF);
    const float* kk = K + ((size_t)o*CC + i)*25;   // K1[i][o] = K[o][i]
    float mn2 = 1e30f, mx2 = -1e30f;
    #pragma unroll
    for (int t = 0; t < 25; t++) {
        v[t] = (1.f - ALPHA_)*kk[t] + ALPHA_*((v[t] - mn)*inv);
        mn2 = fminf(mn2, v[t]); mx2 = fmaxf(mx2, v[t]);
    }
    float inv2 = 1.f / (mx2 - mn2 + EPSF);
    float* w = g_W2 + (size_t)g*25;
    #pragma unroll
    for (int t = 0; t < 25; t++) w[t] = (v[t] - mn2)*inv2;
}

// ---------------- winner-sparse conv2 + gather + output (f-pair packed) ----
// grid (b=16, pg=8); 128 threads = 16 f-pairs x 8 q-groups (7 outputs each)
#define SIN_ULL (5*32*61)              // 9760
#define SW_ULL  (16*801)               // 12816
#define SMEM_OUT ((SIN_ULL + SW_ULL)*8)

__global__ void __launch_bounds__(128) k_out(float* __restrict__ out) {
    int b = blockIdx.x, pg = blockIdx.y;
    int tid = threadIdx.x;
    int fl = tid >> 3;                 // f-pair 0..15 -> f = 2fl, 2fl+1
    int qg = tid & 7;
    int q0 = qg * 7;

    extern __shared__ ull sh[];
    ull* sIn = sh;                     // [5][32][61] duplicated {v,v}
    ull* sW  = sh + SIN_ULL;           // [16][801] packed {w_f0, w_f1}
    __shared__ int sFm[32];
    if (tid < 32) sFm[tid] = g_fm[b*FM + tid];
    __syncthreads();

    // packed weights: {W2[win_f0][win_i][t], W2[win_f1][win_i][t]}
    for (int idx = tid; idx < 16*800; idx += 128) {
        int fp = idx / 800, rem = idx - fp*800;
        int i = rem / 25, t = rem - i*25;
        float w0 = g_W2[((size_t)sFm[2*fp  ]*CC + sFm[i])*25 + t];
        float w1 = g_W2[((size_t)sFm[2*fp+1]*CC + sFm[i])*25 + t];
        sW[fp*801 + rem] = pack2(w0, w1);
    }

    const float* AbB = g_Ab + (size_t)b*CC*HW;
    int p0 = pg * 7;

    // prologue: padded rows p0..p0+3 (reflect map applied on the fly)
    #pragma unroll
    for (int r = 0; r < 4; r++) {
        int row = p0 + r, slot = row % 5, sr = m60(row);
        for (int idx = tid; idx < 32*60; idx += 128) {
            int i = idx / 60, col = idx - i*60;
            float v = AbB[(size_t)sFm[i]*HW + sr*56 + m60(col)];
            sIn[(slot*32 + i)*61 + col] = pack2(v, v);
        }
    }

    const ull* wbase = sW + fl*801;
    for (int p = p0; p < p0 + 7; p++) {
        __syncthreads();
        {   // padded row p+4
            int row = p + 4, slot = row % 5, sr = m60(row);
            for (int idx = tid; idx < 32*60; idx += 128) {
                int i = idx / 60, col = idx - i*60;
                float v = AbB[(size_t)sFm[i]*HW + sr*56 + m60(col)];
                sIn[(slot*32 + i)*61 + col] = pack2(v, v);
            }
        }
        __syncthreads();

        ull acc[7];
        #pragma unroll
        for (int j = 0; j < 7; j++) acc[j] = 0ull;

        #pragma unroll 1
        for (int i = 0; i < 32; i++) {
            #pragma unroll
            for (int u = 0; u < 5; u++) {
                const ull* wr = wbase + i*25 + u*5;
                ull w0 = wr[0], w1 = wr[1], w2 = wr[2], w3 = wr[3], w4 = wr[4];
                const ull* rp = sIn + (((p + u) % 5)*32 + i)*61 + q0;
                #pragma unroll
                for (int cc = 0; cc < 11; cc++) {
                    ull v = rp[cc];
                    if (cc <= 6)            ffma2(acc[cc],   v, w0);
                    if (cc >= 1 && cc <= 7) ffma2(acc[cc-1], v, w1);
                    if (cc >= 2 && cc <= 8) ffma2(acc[cc-2], v, w2);
                    if (cc >= 3 && cc <= 9) ffma2(acc[cc-3], v, w3);
                    if (cc >= 4)            ffma2(acc[cc-4], v, w4);
                }
            }
        }

        int f0 = 2*fl, f1 = f0 + 1;
        const float* a0r = AbB + (size_t)sFm[f0]*HW + p*56 + q0;
        const float* a1r = AbB + (size_t)sFm[f1]*HW + p*56 + q0;
        float* o0 = out + ((size_t)(b*FM + f0)*56 + p)*56 + q0;
        float* o1 = out + ((size_t)(b*FM + f1)*56 + p)*56 + q0;
        #pragma unroll
        for (int j = 0; j < 7; j++) {
            float2 v = unpk(acc[j]);
            o0[j] = a0r[j] + THETA_ * (v.x * (1.f/32.f));
            o1[j] = a1r[j] + THETA_ * (v.y * (1.f/32.f));
        }
    }
}

// ---------------- launch ----------------
extern "C" void kernel_launch(void* const* d_in, const int* in_sizes, int n_in,
                              void* d_out, int out_size) {
    const float* A     = (const float*)d_in[0];
    const float* K     = (const float*)d_in[1];
    const float* noise = (const float*)d_in[2];
    float* out = (float*)d_out;

    k_prep<<<BB*CC, 256>>>(A, noise);
    k_zero<<<(CC*CC*25 + 255)/256, 256>>>();
    k_win<<<1, BB*FM>>>();
    k_kch<<<dim3(BB, 4, 4), 128>>>();
    k_w2<<<(CC*CC + 255)/256, 256>>>(K);

    cudaFuncSetAttribute(k_out, cudaFuncAttributeMaxDynamicSharedMemorySize, SMEM_OUT);
    k_out<<<dim3(BB, 8), 128, SMEM_OUT>>>(out);
}

// round 4
// speedup vs baseline: 1.2625x; 1.1908x over previous
#include <cuda_runtime.h>
#include <cstdint>

#define BB 16
#define FM 32
#define CC 128
#define HW 3136
#define ETA 0.1f
#define ALPHA_ 0.1f
#define THETA_ 0.1f
#define EPSF 1e-10f

typedef unsigned long long ull;

// ------------- scratch (static device globals; no allocation) -------------
__device__ float g_Ab[BB*CC*HW];        // clip(tile(symm_pad(A,2)) + eta*noise, 0)
__device__ float g_s[BB*CC];            // per-(b,c) spatial sum
__device__ int   g_fm[BB*FM];           // winner channel per (b,f)
__device__ float g_Kch[CC*CC*25];       // K_change [c][a][x*5+y]
__device__ float g_W2[CC*CC*25];        // conv2 weights [o][i][t]

// ---------------- packed f32x2 helpers ----------------
__device__ __forceinline__ ull pack2(float x, float y) {
    ull r; asm("mov.b64 %0, {%1,%2};" : "=l"(r) : "f"(x), "f"(y)); return r;
}
__device__ __forceinline__ void ffma2(ull& d, ull a, ull b) {
    asm("fma.rn.f32x2 %0, %1, %2, %3;" : "=l"(d) : "l"(a), "l"(b), "l"(d));
}
__device__ __forceinline__ float2 unpk(ull v) {
    float2 r; asm("mov.b64 {%0,%1}, %2;" : "=f"(r.x), "=f"(r.y) : "l"(v)); return r;
}

// symm_pad(.,2) index map on a 56 axis: 0->3, 1->2, 54->53, 55->52
__device__ __forceinline__ int m56(int h) {
    return h < 2 ? 3 - h : (h >= 54 ? 107 - h : h);
}
// pad_activations row/col map on the 60 axis (includes clobbering semantics)
__device__ __forceinline__ int m60(int r) {
    return r < 4 ? 5 - r : (r < 56 ? r - 2 : 109 - r);
}

// ---------------- kernel 1: Ab + per-channel sums ----------------
__global__ void k_prep(const float* __restrict__ A, const float* __restrict__ noise) {
    int bid = blockIdx.x;              // b*128 + c
    int b = bid >> 7, c = bid & 127;
    int f = c & 31;
    const float* Ap = A + (size_t)(b*FM + f)*HW;
    const float* Np = noise + (size_t)bid*HW;
    float* Op = g_Ab + (size_t)bid*HW;
    float sum = 0.f;
    for (int idx = threadIdx.x; idx < HW; idx += 256) {
        int h = idx / 56, w = idx - h*56;
        float v = fmaxf(Ap[m56(h)*56 + m56(w)] + ETA*Np[idx], 0.f);
        Op[idx] = v;
        sum += v;
    }
    __shared__ float red[8];
    #pragma unroll
    for (int o = 16; o; o >>= 1) sum += __shfl_xor_sync(~0u, sum, o);
    if ((threadIdx.x & 31) == 0) red[threadIdx.x >> 5] = sum;
    __syncthreads();
    if (threadIdx.x < 8) {
        float s2 = red[threadIdx.x];
        #pragma unroll
        for (int o = 4; o; o >>= 1) s2 += __shfl_xor_sync(0xffu, s2, o);
        if (threadIdx.x == 0) g_s[bid] = s2;
    }
}

// ---------------- zero K_change accumulator ----------------
__global__ void k_zero() {
    int i = blockIdx.x*blockDim.x + threadIdx.x;
    if (i < CC*CC*25) g_Kch[i] = 0.f;
}

// ---------------- winners (softmax sums to 1 -> argmax on sum(Ab)) --------
__global__ void k_win() {
    int t = threadIdx.x;               // b*32 + f
    int b = t >> 5, f = t & 31;
    float best = g_s[b*CC + f];
    int wr = 0;
    #pragma unroll
    for (int r = 1; r < 4; r++) {
        float v = g_s[b*CC + r*FM + f];
        if (v > best) { best = v; wr = r; }
    }
    g_fm[t] = wr*FM + f;
}

// ---------------- K_change: single-wave, pipelined, f32x2 ----------------
// grid (b=16, cwt=4, at=2) = 128 blocks; 256 threads = 8 winners x 32 a-pairs
#define SLOTS 6
#define CHS 66                           // channel-dim stride (floats)
#define SAB_FLOATS (SLOTS*60*CHS)        // 23760
#define SMEM_KCH (SAB_FLOATS*4 + 2*8*56*8)   // 95040 + 7168 = 102208 B

__global__ void __launch_bounds__(256) k_kch() {
    int b = blockIdx.x, cwt = blockIdx.y, at = blockIdx.z;
    int tid = threadIdx.x;
    int al = tid & 31;                   // a-pair -> channels (2al, 2al+1) of 64
    int cl = tid >> 5;                   // winner slot 0..7 (one per warp)
    int a0 = at*64;

    extern __shared__ char smraw[];
    float* sAb  = (float*)smraw;                      // [6][60][66]
    ull*   sAm2 = (ull*)(smraw + SAB_FLOATS*4);       // [2][8][56] {v,v}
    __shared__ int sC[8];

    if (tid < 8) sC[tid] = g_fm[b*FM + cwt*8 + tid];
    for (int i = tid; i < SAB_FLOATS; i += 256) sAb[i] = 0.f;
    __syncthreads();

    const float* AbB = g_Ab + (size_t)b*CC*HW;

    // prologue: data rows 0..2 -> slots 0..2 (cols 2..57); slots 3..5 stay zero
    for (int r = 0; r < 3; r++)
        for (int idx = tid; idx < 64*56; idx += 256) {
            int ch = idx / 56, col = idx - ch*56;
            sAb[(r*60 + col + 2)*CHS + ch] = AbB[(size_t)(a0+ch)*HW + r*56 + col];
        }
    // am row 0 -> buffer 0
    for (int idx = tid; idx < 8*56; idx += 256) {
        int cj = idx / 56, col = idx - cj*56;
        float v = AbB[(size_t)sC[cj]*HW + col];
        sAm2[cj*56 + col] = pack2(v, v);
    }
    int myc = sC[cl];
    __syncthreads();

    ull acc[5][5];
    #pragma unroll
    for (int x = 0; x < 5; x++)
        #pragma unroll
        for (int y = 0; y < 5; y++) acc[x][y] = 0ull;

    for (int h = 0; h < 56; h++) {
        // ---- prefetch data row h+3 into regs (hidden behind compute) ----
        float pf[14];
        int prow = h + 3;
        bool pv = prow < 56;
        #pragma unroll
        for (int j = 0; j < 14; j++) {
            int idx = tid + j*256;
            int ch = idx / 56, col = idx - ch*56;
            pf[j] = pv ? AbB[(size_t)(a0+ch)*HW + prow*56 + col] : 0.f;
        }
        // ---- prefetch winner row h+1 ----
        float pa0 = 0.f, pa1 = 0.f;
        int arow = h + 1;
        if (arow < 56) {
            int cj0 = tid / 56, co0 = tid - cj0*56;
            pa0 = AbB[(size_t)sC[cj0]*HW + arow*56 + co0];
            int i1 = tid + 256;
            if (i1 < 448) {
                int cj1 = i1 / 56, co1 = i1 - cj1*56;
                pa1 = AbB[(size_t)sC[cj1]*HW + arow*56 + co1];
            }
        }

        // ---- compute row h ----
        const char* rxp[5];
        #pragma unroll
        for (int x = 0; x < 5; x++) {
            int slot = (h + 8 - x) % 6;           // row h+2-x
            rxp[x] = (const char*)(sAb + slot*60*CHS + 2*al);
        }
        const ull* am = sAm2 + (size_t)(h & 1)*8*56 + cl*56;

        ull rg[5][5];
        #pragma unroll
        for (int x = 0; x < 5; x++)
            #pragma unroll
            for (int j = 0; j < 5; j++)
                rg[x][j] = *(const ull*)(rxp[x] + j*(CHS*4));

        #pragma unroll 1
        for (int wb = 0; wb < 55; wb += 5) {
            #pragma unroll
            for (int k = 0; k < 5; k++) {
                ull a = am[wb + k];
                #pragma unroll
                for (int x = 0; x < 5; x++) {
                    #pragma unroll
                    for (int y = 0; y < 5; y++)
                        ffma2(acc[x][y], a, rg[x][(k + 4 - y) % 5]);
                    rg[x][k] = *(const ull*)(rxp[x] + (wb + k + 5)*(CHS*4));
                }
            }
        }
        {   // w = 55 (ring phase k=0)
            ull a = am[55];
            #pragma unroll
            for (int x = 0; x < 5; x++)
                #pragma unroll
                for (int y = 0; y < 5; y++)
                    ffma2(acc[x][y], a, rg[x][(4 - y) % 5]);
        }

        // ---- commit prefetched row to slot (h+3)%6 (outside live window) ----
        {
            int slot = (h + 3) % 6;
            #pragma unroll
            for (int j = 0; j < 14; j++) {
                int idx = tid + j*256;
                int ch = idx / 56, col = idx - ch*56;
                sAb[(slot*60 + col + 2)*CHS + ch] = pf[j];
            }
            if (arow < 56) {
                ull* dst = sAm2 + (size_t)(arow & 1)*8*56;
                int cj0 = tid / 56, co0 = tid - cj0*56;
                dst[cj0*56 + co0] = pack2(pa0, pa0);
                int i1 = tid + 256;
                if (i1 < 448) {
                    int cj1 = i1 / 56, co1 = i1 - cj1*56;
                    dst[cj1*56 + co1] = pack2(pa1, pa1);
                }
            }
        }
        __syncthreads();
    }

    float* dst = g_Kch + ((size_t)myc*CC + (a0 + 2*al))*25;
    #pragma unroll
    for (int x = 0; x < 5; x++)
        #pragma unroll
        for (int y = 0; y < 5; y++) {
            float2 v = unpk(acc[x][y]);
            atomicAdd(&dst[x*5 + y],      v.x * (1.f/2048.f));
            atomicAdd(&dst[25 + x*5 + y], v.y * (1.f/2048.f));
        }
}

// ---------------- W2 = minmax(0.9*K1 + 0.1*minmax(K_change)) ---------------
__global__ void k_w2(const float* __restrict__ K) {
    int g = blockIdx.x*blockDim.x + threadIdx.x;
    if (g >= CC*CC) return;
    int o = g >> 7, i = g & 127;
    const float* kch = g_Kch + ((size_t)i*CC + o)*25;
    float v[25];
    float mn = 1e30f, mx = -1e30f;
    #pragma unroll
    for (int t = 0; t < 25; t++) { v[t] = kch[t]; mn = fminf(mn, v[t]); mx = fmaxf(mx, v[t]); }
    float inv = 1.f / (mx - mn + EPSF);
    const float* kk = K + ((size_t)o*CC + i)*25;   // K1[i][o] = K[o][i]
    float mn2 = 1e30f, mx2 = -1e30f;
    #pragma unroll
    for (int t = 0; t < 25; t++) {
        v[t] = (1.f - ALPHA_)*kk[t] + ALPHA_*((v[t] - mn)*inv);
        mn2 = fminf(mn2, v[t]); mx2 = fmaxf(mx2, v[t]);
    }
    float inv2 = 1.f / (mx2 - mn2 + EPSF);
    float* w = g_W2 + (size_t)g*25;
    #pragma unroll
    for (int t = 0; t < 25; t++) w[t] = (v[t] - mn2)*inv2;
}

// ---------------- winner-sparse conv2 + gather + output (f-pair packed) ----
// grid (b=16, pg=8); 128 threads = 16 f-pairs x 8 q-groups (7 outputs each)
#define SIN_ULL (5*32*61)              // 9760
#define SW_ULL  (16*801)               // 12816
#define SMEM_OUT ((SIN_ULL + SW_ULL)*8)

__global__ void __launch_bounds__(128) k_out(float* __restrict__ out) {
    int b = blockIdx.x, pg = blockIdx.y;
    int tid = threadIdx.x;
    int fl = tid >> 3;                 // f-pair 0..15 -> f = 2fl, 2fl+1
    int qg = tid & 7;
    int q0 = qg * 7;

    extern __shared__ ull sh[];
    ull* sIn = sh;                     // [5][32][61] duplicated {v,v}
    ull* sW  = sh + SIN_ULL;           // [16][801] packed {w_f0, w_f1}
    __shared__ int sFm[32];
    if (tid < 32) sFm[tid] = g_fm[b*FM + tid];
    __syncthreads();

    for (int idx = tid; idx < 16*800; idx += 128) {
        int fp = idx / 800, rem = idx - fp*800;
        int i = rem / 25, t = rem - i*25;
        float w0 = g_W2[((size_t)sFm[2*fp  ]*CC + sFm[i])*25 + t];
        float w1 = g_W2[((size_t)sFm[2*fp+1]*CC + sFm[i])*25 + t];
        sW[fp*801 + rem] = pack2(w0, w1);
    }

    const float* AbB = g_Ab + (size_t)b*CC*HW;
    int p0 = pg * 7;

    #pragma unroll
    for (int r = 0; r < 4; r++) {
        int row = p0 + r, slot = row % 5, sr = m60(row);
        for (int idx = tid; idx < 32*60; idx += 128) {
            int i = idx / 60, col = idx - i*60;
            float v = AbB[(size_t)sFm[i]*HW + sr*56 + m60(col)];
            sIn[(slot*32 + i)*61 + col] = pack2(v, v);
        }
    }

    const ull* wbase = sW + fl*801;
    for (int p = p0; p < p0 + 7; p++) {
        __syncthreads();
        {
            int row = p + 4, slot = row % 5, sr = m60(row);
            for (int idx = tid; idx < 32*60; idx += 128) {
                int i = idx / 60, col = idx - i*60;
                float v = AbB[(size_t)sFm[i]*HW + sr*56 + m60(col)];
                sIn[(slot*32 + i)*61 + col] = pack2(v, v);
            }
        }
        __syncthreads();

        ull acc[7];
        #pragma unroll
        for (int j = 0; j < 7; j++) acc[j] = 0ull;

        #pragma unroll 1
        for (int i = 0; i < 32; i++) {
            #pragma unroll
            for (int u = 0; u < 5; u++) {
                const ull* wr = wbase + i*25 + u*5;
                ull w0 = wr[0], w1 = wr[1], w2 = wr[2], w3 = wr[3], w4 = wr[4];
                const ull* rp = sIn + (((p + u) % 5)*32 + i)*61 + q0;
                #pragma unroll
                for (int cc = 0; cc < 11; cc++) {
                    ull v = rp[cc];
                    if (cc <= 6)            ffma2(acc[cc],   v, w0);
                    if (cc >= 1 && cc <= 7) ffma2(acc[cc-1], v, w1);
                    if (cc >= 2 && cc <= 8) ffma2(acc[cc-2], v, w2);
                    if (cc >= 3 && cc <= 9) ffma2(acc[cc-3], v, w3);
                    if (cc >= 4)            ffma2(acc[cc-4], v, w4);
                }
            }
        }

        int f0 = 2*fl, f1 = f0 + 1;
        const float* a0r = AbB + (size_t)sFm[f0]*HW + p*56 + q0;
        const float* a1r = AbB + (size_t)sFm[f1]*HW + p*56 + q0;
        float* o0 = out + ((size_t)(b*FM + f0)*56 + p)*56 + q0;
        float* o1 = out + ((size_t)(b*FM + f1)*56 + p)*56 + q0;
        #pragma unroll
        for (int j = 0; j < 7; j++) {
            float2 v = unpk(acc[j]);
            o0[j] = a0r[j] + THETA_ * (v.x * (1.f/32.f));
            o1[j] = a1r[j] + THETA_ * (v.y * (1.f/32.f));
        }
    }
}

// ---------------- launch ----------------
extern "C" void kernel_launch(void* const* d_in, const int* in_sizes, int n_in,
                              void* d_out, int out_size) {
    const float* A     = (const float*)d_in[0];
    const float* K     = (const float*)d_in[1];
    const float* noise = (const float*)d_in[2];
    float* out = (float*)d_out;

    k_prep<<<BB*CC, 256>>>(A, noise);
    k_zero<<<(CC*CC*25 + 255)/256, 256>>>();
    k_win<<<1, BB*FM>>>();

    cudaFuncSetAttribute(k_kch, cudaFuncAttributeMaxDynamicSharedMemorySize, SMEM_KCH);
    k_kch<<<dim3(BB, 4, 2), 256, SMEM_KCH>>>();

    k_w2<<<(CC*CC + 255)/256, 256>>>(K);

    cudaFuncSetAttribute(k_out, cudaFuncAttributeMaxDynamicSharedMemorySize, SMEM_OUT);
    k_out<<<dim3(BB, 8), 128, SMEM_OUT>>>(out);
}

// round 5
// speedup vs baseline: 1.4791x; 1.1715x over previous
#include <cuda_runtime.h>
#include <cstdint>

#define BB 16
#define FM 32
#define CC 128
#define HW 3136
#define ETA 0.1f
#define ALPHA_ 0.1f
#define THETA_ 0.1f
#define EPSF 1e-10f

typedef unsigned long long ull;

// ------------- scratch (static device globals; no allocation) -------------
__device__ float g_Ab[BB*CC*HW];        // clip(tile(symm_pad(A,2)) + eta*noise, 0)
__device__ float g_s[BB*CC];            // per-(b,c) spatial sum
__device__ int   g_fm[BB*FM];           // winner channel per (b,f)
__device__ float g_Kch[CC*CC*25];       // K_change [c][a][x*5+y]
__device__ float g_W2[CC*CC*25];        // conv2 weights [o][i][t]

// ---------------- packed f32x2 helpers ----------------
__device__ __forceinline__ ull pack2(float x, float y) {
    ull r; asm("mov.b64 %0, {%1,%2};" : "=l"(r) : "f"(x), "f"(y)); return r;
}
__device__ __forceinline__ void ffma2(ull& d, ull a, ull b) {
    asm("fma.rn.f32x2 %0, %1, %2, %3;" : "=l"(d) : "l"(a), "l"(b), "l"(d));
}
__device__ __forceinline__ float2 unpk(ull v) {
    float2 r; asm("mov.b64 {%0,%1}, %2;" : "=f"(r.x), "=f"(r.y) : "l"(v)); return r;
}

// symm_pad(.,2) index map on a 56 axis: 0->3, 1->2, 54->53, 55->52
__device__ __forceinline__ int m56(int h) {
    return h < 2 ? 3 - h : (h >= 54 ? 107 - h : h);
}
// pad_activations row/col map on the 60 axis (includes clobbering semantics)
__device__ __forceinline__ int m60(int r) {
    return r < 4 ? 5 - r : (r < 56 ? r - 2 : 109 - r);
}

// ---------------- kernel 1: Ab + per-channel sums (+ zero g_Kch) -----------
__global__ void k_prep(const float* __restrict__ A, const float* __restrict__ noise) {
    int bid = blockIdx.x;              // b*128 + c
    // fold K_change zeroing in: 2048 blocks x 200 floats = 409600
    {
        int z0 = bid*200;
        for (int j = threadIdx.x; j < 200; j += 256) g_Kch[z0 + j] = 0.f;
    }
    int b = bid >> 7, c = bid & 127;
    int f = c & 31;
    const float* Ap = A + (size_t)(b*FM + f)*HW;
    const float* Np = noise + (size_t)bid*HW;
    float* Op = g_Ab + (size_t)bid*HW;
    float sum = 0.f;
    for (int idx = threadIdx.x; idx < HW; idx += 256) {
        int h = idx / 56, w = idx - h*56;
        float v = fmaxf(Ap[m56(h)*56 + m56(w)] + ETA*Np[idx], 0.f);
        Op[idx] = v;
        sum += v;
    }
    __shared__ float red[8];
    #pragma unroll
    for (int o = 16; o; o >>= 1) sum += __shfl_xor_sync(~0u, sum, o);
    if ((threadIdx.x & 31) == 0) red[threadIdx.x >> 5] = sum;
    __syncthreads();
    if (threadIdx.x < 8) {
        float s2 = red[threadIdx.x];
        #pragma unroll
        for (int o = 4; o; o >>= 1) s2 += __shfl_xor_sync(0xffu, s2, o);
        if (threadIdx.x == 0) g_s[bid] = s2;
    }
}

// ---------------- winners (softmax sums to 1 -> argmax on sum(Ab)) --------
__global__ void k_win() {
    int t = threadIdx.x;               // b*32 + f
    int b = t >> 5, f = t & 31;
    float best = g_s[b*CC + f];
    int wr = 0;
    #pragma unroll
    for (int r = 1; r < 4; r++) {
        float v = g_s[b*CC + r*FM + f];
        if (v > best) { best = v; wr = r; }
    }
    g_fm[t] = wr*FM + f;
}

// ---------------- K_change: crossbar-halved warp shape --------------------
// grid (b=16, cwt=2, at=4) = 128 blocks; 256 threads:
// warp = 2 winners x 16 a-pairs; block = 16 winners x 32 channels
#define CHS 34                           // channel stride (floats), 32ch + pad
#define SAB_FLOATS (6*60*CHS)            // 12240
#define SAM_ULL (2*16*56)                // double-buffered winner rows {v,v}
#define SMEM_KCH (SAB_FLOATS*4 + SAM_ULL*8)   // 48960 + 14336 = 63296 B

__global__ void __launch_bounds__(256) k_kch() {
    int b = blockIdx.x, cwt = blockIdx.y, at = blockIdx.z;
    int tid = threadIdx.x;
    int lane = tid & 31, wid = tid >> 5;
    int al = lane & 15;                  // a-pair -> channels (2al, 2al+1) of 32
    int cl = wid*2 + (lane >> 4);        // winner slot 0..15
    int a0 = at*32;

    extern __shared__ char smraw[];
    float* sAb  = (float*)smraw;                      // [6][60][34]
    ull*   sAm2 = (ull*)(smraw + SAB_FLOATS*4);       // [2][16][56]
    __shared__ int sC[16];

    if (tid < 16) sC[tid] = g_fm[b*FM + cwt*16 + tid];
    for (int i = tid; i < SAB_FLOATS; i += 256) sAb[i] = 0.f;
    __syncthreads();

    const float* AbB = g_Ab + (size_t)b*CC*HW;

    // prologue: data rows 0..2 -> slots 0..2 (cols 2..57); slots 3..5 stay zero
    for (int r = 0; r < 3; r++)
        for (int idx = tid; idx < 32*56; idx += 256) {
            int ch = idx / 56, col = idx - ch*56;
            sAb[(r*60 + col + 2)*CHS + ch] = AbB[(size_t)(a0+ch)*HW + r*56 + col];
        }
    // am row 0 -> buffer 0
    for (int idx = tid; idx < 16*56; idx += 256) {
        int cj = idx / 56, col = idx - cj*56;
        float v = AbB[(size_t)sC[cj]*HW + col];
        sAm2[cj*56 + col] = pack2(v, v);
    }
    int myc = sC[cl];
    __syncthreads();

    ull acc[5][5];
    #pragma unroll
    for (int x = 0; x < 5; x++)
        #pragma unroll
        for (int y = 0; y < 5; y++) acc[x][y] = 0ull;

    for (int h = 0; h < 56; h++) {
        // ---- prefetch data row h+3 into regs (hidden behind compute) ----
        float pf[7];
        int prow = h + 3;
        bool pv = prow < 56;
        #pragma unroll
        for (int j = 0; j < 7; j++) {
            int idx = tid + j*256;
            int ch = idx / 56, col = idx - ch*56;
            pf[j] = pv ? AbB[(size_t)(a0+ch)*HW + prow*56 + col] : 0.f;
        }
        // ---- prefetch winner row h+1 (16x56 = 896 values) ----
        float pa[4];
        int arow = h + 1;
        #pragma unroll
        for (int j = 0; j < 4; j++) {
            int idx = tid + j*256;
            pa[j] = 0.f;
            if (arow < 56 && idx < 16*56) {
                int cj = idx / 56, co = idx - cj*56;
                pa[j] = AbB[(size_t)sC[cj]*HW + arow*56 + co];
            }
        }

        // ---- compute row h ----
        const char* rxp[5];
        #pragma unroll
        for (int x = 0; x < 5; x++) {
            int slot = (h + 8 - x) % 6;           // row h+2-x
            rxp[x] = (const char*)(sAb + slot*60*CHS + 2*al);
        }
        const ull* am = sAm2 + (size_t)(h & 1)*16*56 + cl*56;

        ull rg[5][5];
        #pragma unroll
        for (int x = 0; x < 5; x++)
            #pragma unroll
            for (int j = 0; j < 5; j++)
                rg[x][j] = *(const ull*)(rxp[x] + j*(CHS*4));

        #pragma unroll 1
        for (int wb = 0; wb < 55; wb += 5) {
            #pragma unroll
            for (int k = 0; k < 5; k++) {
                ull a = am[wb + k];
                #pragma unroll
                for (int x = 0; x < 5; x++) {
                    #pragma unroll
                    for (int y = 0; y < 5; y++)
                        ffma2(acc[x][y], a, rg[x][(k + 4 - y) % 5]);
                    rg[x][k] = *(const ull*)(rxp[x] + (wb + k + 5)*(CHS*4));
                }
            }
        }
        {   // w = 55 (ring phase k=0)
            ull a = am[55];
            #pragma unroll
            for (int x = 0; x < 5; x++)
                #pragma unroll
                for (int y = 0; y < 5; y++)
                    ffma2(acc[x][y], a, rg[x][(4 - y) % 5]);
        }

        // ---- commit prefetched data to slot (h+3)%6 (outside live window) ----
        {
            int slot = (h + 3) % 6;
            #pragma unroll
            for (int j = 0; j < 7; j++) {
                int idx = tid + j*256;
                int ch = idx / 56, col = idx - ch*56;
                sAb[(slot*60 + col + 2)*CHS + ch] = pf[j];
            }
            if (arow < 56) {
                ull* dst = sAm2 + (size_t)(arow & 1)*16*56;
                #pragma unroll
                for (int j = 0; j < 4; j++) {
                    int idx = tid + j*256;
                    if (idx < 16*56) {
                        int cj = idx / 56, co = idx - cj*56;
                        dst[cj*56 + co] = pack2(pa[j], pa[j]);
                    }
                }
            }
        }
        __syncthreads();
    }

    float* dst = g_Kch + ((size_t)myc*CC + (a0 + 2*al))*25;
    #pragma unroll
    for (int x = 0; x < 5; x++)
        #pragma unroll
        for (int y = 0; y < 5; y++) {
            float2 v = unpk(acc[x][y]);
            atomicAdd(&dst[x*5 + y],      v.x * (1.f/2048.f));
            atomicAdd(&dst[25 + x*5 + y], v.y * (1.f/2048.f));
        }
}

// ---------------- W2 = minmax(0.9*K1 + 0.1*minmax(K_change)) ---------------
__global__ void k_w2(const float* __restrict__ K) {
    int g = blockIdx.x*blockDim.x + threadIdx.x;
    if (g >= CC*CC) return;
    int o = g >> 7, i = g & 127;
    const float* kch = g_Kch + ((size_t)i*CC + o)*25;
    float v[25];
    float mn = 1e30f, mx = -1e30f;
    #pragma unroll
    for (int t = 0; t < 25; t++) { v[t] = kch[t]; mn = fminf(mn, v[t]); mx = fmaxf(mx, v[t]); }
    float inv = 1.f / (mx - mn + EPSF);
    const float* kk = K + ((size_t)o*CC + i)*25;   // K1[i][o] = K[o][i]
    float mn2 = 1e30f, mx2 = -1e30f;
    #pragma unroll
    for (int t = 0; t < 25; t++) {
        v[t] = (1.f - ALPHA_)*kk[t] + ALPHA_*((v[t] - mn)*inv);
        mn2 = fminf(mn2, v[t]); mx2 = fmaxf(mx2, v[t]);
    }
    float inv2 = 1.f / (mx2 - mn2 + EPSF);
    float* w = g_W2 + (size_t)g*25;
    #pragma unroll
    for (int t = 0; t < 25; t++) w[t] = (v[t] - mn2)*inv2;
}

// ---------------- winner-sparse conv2 + gather + output --------------------
// grid (b=16, pg=8); 256 threads = 2 i-halves x (16 f-pairs x 8 q-groups)
#define SIN_ULL (5*32*61)              // 9760
#define SW_ULL  (16*801)               // 12816
#define SRED_ULL (128*7)               // 896
#define SMEM_OUT ((SIN_ULL + SW_ULL + SRED_ULL)*8)   // 187776 B

__global__ void __launch_bounds__(256) k_out(float* __restrict__ out) {
    int b = blockIdx.x, pg = blockIdx.y;
    int tid = threadIdx.x;
    int g = tid >> 7;                  // i-half: 0 -> i 0..15, 1 -> i 16..31
    int t7 = tid & 127;
    int fl = t7 >> 3;                  // f-pair 0..15 -> f = 2fl, 2fl+1
    int qg = t7 & 7;
    int q0 = qg * 7;

    extern __shared__ ull sh[];
    ull* sIn  = sh;                    // [5][32][61] duplicated {v,v}
    ull* sW   = sh + SIN_ULL;          // [16][801] packed {w_f0, w_f1}
    ull* sRed = sh + SIN_ULL + SW_ULL; // [128][7] partial acc from g=1
    __shared__ int sFm[32];
    if (tid < 32) sFm[tid] = g_fm[b*FM + tid];
    __syncthreads();

    for (int idx = tid; idx < 16*800; idx += 256) {
        int fp = idx / 800, rem = idx - fp*800;
        int i = rem / 25, t = rem - i*25;
        float w0 = g_W2[((size_t)sFm[2*fp  ]*CC + sFm[i])*25 + t];
        float w1 = g_W2[((size_t)sFm[2*fp+1]*CC + sFm[i])*25 + t];
        sW[fp*801 + rem] = pack2(w0, w1);
    }

    const float* AbB = g_Ab + (size_t)b*CC*HW;
    int p0 = pg * 7;

    #pragma unroll
    for (int r = 0; r < 4; r++) {
        int row = p0 + r, slot = row % 5, sr = m60(row);
        for (int idx = tid; idx < 32*60; idx += 256) {
            int i = idx / 60, col = idx - i*60;
            float v = AbB[(size_t)sFm[i]*HW + sr*56 + m60(col)];
            sIn[(slot*32 + i)*61 + col] = pack2(v, v);
        }
    }

    const ull* wbase = sW + fl*801;
    int i0 = g*16;
    for (int p = p0; p < p0 + 7; p++) {
        __syncthreads();
        {
            int row = p + 4, slot = row % 5, sr = m60(row);
            for (int idx = tid; idx < 32*60; idx += 256) {
                int i = idx / 60, col = idx - i*60;
                float v = AbB[(size_t)sFm[i]*HW + sr*56 + m60(col)];
                sIn[(slot*32 + i)*61 + col] = pack2(v, v);
            }
        }
        __syncthreads();

        ull acc[7];
        #pragma unroll
        for (int j = 0; j < 7; j++) acc[j] = 0ull;

        #pragma unroll 1
        for (int i = i0; i < i0 + 16; i++) {
            #pragma unroll
            for (int u = 0; u < 5; u++) {
                const ull* wr = wbase + i*25 + u*5;
                ull w0 = wr[0], w1 = wr[1], w2 = wr[2], w3 = wr[3], w4 = wr[4];
                const ull* rp = sIn + (((p + u) % 5)*32 + i)*61 + q0;
                #pragma unroll
                for (int cc = 0; cc < 11; cc++) {
                    ull v = rp[cc];
                    if (cc <= 6)            ffma2(acc[cc],   v, w0);
                    if (cc >= 1 && cc <= 7) ffma2(acc[cc-1], v, w1);
                    if (cc >= 2 && cc <= 8) ffma2(acc[cc-2], v, w2);
                    if (cc >= 3 && cc <= 9) ffma2(acc[cc-3], v, w3);
                    if (cc >= 4)            ffma2(acc[cc-4], v, w4);
                }
            }
        }

        if (g == 1) {
            #pragma unroll
            for (int j = 0; j < 7; j++) sRed[t7*7 + j] = acc[j];
        }
        __syncthreads();
        if (g == 0) {
            int f0 = 2*fl, f1 = f0 + 1;
            const float* a0r = AbB + (size_t)sFm[f0]*HW + p*56 + q0;
            const float* a1r = AbB + (size_t)sFm[f1]*HW + p*56 + q0;
            float* o0 = out + ((size_t)(b*FM + f0)*56 + p)*56 + q0;
            float* o1 = out + ((size_t)(b*FM + f1)*56 + p)*56 + q0;
            #pragma unroll
            for (int j = 0; j < 7; j++) {
                float2 v = unpk(acc[j]);
                float2 r = unpk(sRed[t7*7 + j]);
                o0[j] = a0r[j] + THETA_ * ((v.x + r.x) * (1.f/32.f));
                o1[j] = a1r[j] + THETA_ * ((v.y + r.y) * (1.f/32.f));
            }
        }
    }
}

// ---------------- launch ----------------
extern "C" void kernel_launch(void* const* d_in, const int* in_sizes, int n_in,
                              void* d_out, int out_size) {
    const float* A     = (const float*)d_in[0];
    const float* K     = (const float*)d_in[1];
    const float* noise = (const float*)d_in[2];
    float* out = (float*)d_out;

    k_prep<<<BB*CC, 256>>>(A, noise);
    k_win<<<1, BB*FM>>>();

    cudaFuncSetAttribute(k_kch, cudaFuncAttributeMaxDynamicSharedMemorySize, SMEM_KCH);
    k_kch<<<dim3(BB, 2, 4), 256, SMEM_KCH>>>();

    k_w2<<<(CC*CC + 255)/256, 256>>>(K);

    cudaFuncSetAttribute(k_out, cudaFuncAttributeMaxDynamicSharedMemorySize, SMEM_OUT);
    k_out<<<dim3(BB, 8), 256, SMEM_OUT>>>(out);
}